// round 16
// baseline (speedup 1.0000x reference)
#include <cuda_runtime.h>
#include <cuda_fp16.h>
#include <cstdint>

#define THREADS 128
#define TT      128
#define STRIDE  136                 // fp16 elems per smem row (128 + 8 pad)
#define ROWB    (STRIDE * 2)        // 272 bytes per row
#define TSZ     (128 * STRIDE)      // elems per weight tile
#define NNODE   100000
#define BETA    10.0f
#define V2C     3.5f

__device__ double g_rsum, g_klsum;
__device__ unsigned int g_cnt;

// 10 weight tiles, fp16, N-MAJOR [n][k] layout with row stride 136
enum { T_E0A, T_E0B, T_E1, T_E2, T_E3, T_D0, T_D1, T_D2, T_D3A, T_D3B };
__device__ __align__(16) uint16_t g_w[10 * TSZ];
__device__ __align__(16) uint16_t g_xh[NNODE * 128];

// ---- smem byte offsets ----
#define AOFF      0
#define SLOT(s)   (34816 + (s) * 34816)
#define BIASO(b)  (104448 + (b) * 512)
#define ROWS_S    108544
#define COLS_S    109056
#define KLP       109568
#define RS        110080
#define RED       110592
#define SMEM_TOTAL 110720

struct Params {
    const float* x; const int* row; const int* col; const float* eps;
    const float *eW0,*eb0,*eW1,*eb1,*eW2,*eb2,*eW3,*eb3;
    const float *dW0,*db0,*dW1,*db1,*dW2,*db2,*dW3,*db3;
    float* out; int E; int NX;
};

// ---- helpers ----
__device__ __forceinline__ uint32_t smem_u32(const void* p) {
    uint32_t a;
    asm("{ .reg .u64 t; cvta.to.shared.u64 t, %1; cvt.u32.u64 %0, t; }" : "=r"(a) : "l"(p));
    return a;
}
__device__ __forceinline__ uint32_t pack_h2(float a, float b) {
    __half2 h = __floats2half2_rn(a, b);
    return *(uint32_t*)&h;
}
__device__ __forceinline__ uint32_t hadd2u(uint32_t a, uint32_t b) {
    __half2 r = __hadd2(*(__half2*)&a, *(__half2*)&b);
    return *(uint32_t*)&r;
}
__device__ __forceinline__ uint32_t hrelu2u(uint32_t a) {
    __half2 z = __float2half2_rn(0.f);
    __half2 r = __hmax2(*(__half2*)&a, z);
    return *(uint32_t*)&r;
}
__device__ __forceinline__ float2 h22f2(uint32_t a) {
    return __half22float2(*(__half2*)&a);
}

__device__ __forceinline__ void cp16(uint32_t dst, const void* src) {
    asm volatile("cp.async.cg.shared.global [%0], [%1], 16;" :: "r"(dst), "l"(src));
}
__device__ __forceinline__ void cp4(uint32_t dst, const void* src) {
    asm volatile("cp.async.ca.shared.global [%0], [%1], 4;" :: "r"(dst), "l"(src));
}
#define CP_COMMIT() asm volatile("cp.async.commit_group;" ::: "memory")
#define CP_WAIT0()  asm volatile("cp.async.wait_group 0;"  ::: "memory")
#define CP_WAIT1()  asm volatile("cp.async.wait_group 1;"  ::: "memory")

// A fragment: 16x16 row-major at (m0, k0), non-trans ldmatrix.x4
__device__ __forceinline__ void lda4(uint32_t a[4], uint32_t base, int m0, int k0, int lane) {
    uint32_t addr = base + (uint32_t)(((m0 + (lane & 7) + ((lane & 8) ? 8 : 0)) * STRIDE
                                   + k0 + ((lane & 16) ? 8 : 0)) << 1);
    asm volatile("ldmatrix.sync.aligned.m8n8.x4.shared.b16 {%0,%1,%2,%3}, [%4];"
        : "=r"(a[0]), "=r"(a[1]), "=r"(a[2]), "=r"(a[3]) : "r"(addr));
}

// B fragments from N-MAJOR storage: logical 16(k) x 16(n) at (k0, n0)
__device__ __forceinline__ void ldb4nt(uint32_t b[4], uint32_t base, int k0, int n0, int lane) {
    uint32_t addr = base + (uint32_t)(((n0 + (lane & 7) + ((lane & 16) ? 8 : 0)) * STRIDE
                                   + k0 + ((lane & 8) ? 8 : 0)) << 1);
    asm volatile("ldmatrix.sync.aligned.m8n8.x4.shared.b16 {%0,%1,%2,%3}, [%4];"
        : "=r"(b[0]), "=r"(b[1]), "=r"(b[2]), "=r"(b[3]) : "r"(addr));
}

// fp16-accumulate mma: d (2 regs) chained in place
__device__ __forceinline__ void mma16816h(uint32_t* d, const uint32_t a[4],
                                          uint32_t b0, uint32_t b1) {
    asm volatile("mma.sync.aligned.m16n8k16.row.col.f16.f16.f16.f16 "
        "{%0,%1}, {%2,%3,%4,%5}, {%6,%7}, {%0,%1};"
        : "+r"(d[0]), "+r"(d[1])
        : "r"(a[0]), "r"(a[1]), "r"(a[2]), "r"(a[3]), "r"(b0), "r"(b1));
}

// ---- 32-row warp tile GEMMs, fp16 accumulators, 2-deep B prefetch ----
// ch[64]: [mt(2)][q(8)][4]

template<int KS>
__device__ __forceinline__ void gemm_smemA2h(uint32_t ch[64], uint32_t abase, uint32_t bbase,
                                             int m0, int lane) {
    constexpr int NIT = KS * 8;
    uint32_t a[2][2][4];
    uint32_t b[3][4];
    lda4(a[0][0], abase, m0,      0, lane);
    lda4(a[0][1], abase, m0 + 16, 0, lane);
    ldb4nt(b[0], bbase, 0, 0, lane);
    if (NIT > 1) ldb4nt(b[1], bbase, (1 >> 3) * 16, (1 & 7) * 16, lane);
    #pragma unroll
    for (int it = 0; it < NIT; it++) {
        const int q  = it & 7;
        const int ks = it >> 3;
        const int itp = it + 2;
        if (itp < NIT)
            ldb4nt(b[itp % 3], bbase, (itp >> 3) * 16, (itp & 7) * 16, lane);
        if (q == 0 && ks + 1 < KS) {
            lda4(a[(ks + 1) & 1][0], abase, m0,      (ks + 1) * 16, lane);
            lda4(a[(ks + 1) & 1][1], abase, m0 + 16, (ks + 1) * 16, lane);
        }
        const uint32_t* bc = b[it % 3];
        mma16816h(ch + q * 4,          a[ks & 1][0], bc[0], bc[1]);
        mma16816h(ch + q * 4 + 2,      a[ks & 1][0], bc[2], bc[3]);
        mma16816h(ch + 32 + q * 4,     a[ks & 1][1], bc[0], bc[1]);
        mma16816h(ch + 32 + q * 4 + 2, a[ks & 1][1], bc[2], bc[3]);
    }
}

__device__ __forceinline__ void gemm_regA2h(uint32_t ch[64], const uint32_t areg[64],
                                            uint32_t bbase, int lane) {
    uint32_t b[3][4];
    ldb4nt(b[0], bbase, 0, 0, lane);
    ldb4nt(b[1], bbase, 0, 16, lane);
    #pragma unroll
    for (int it = 0; it < 64; it++) {
        const int q  = it & 7;
        const int ks = it >> 3;
        const int itp = it + 2;
        if (itp < 64)
            ldb4nt(b[itp % 3], bbase, (itp >> 3) * 16, (itp & 7) * 16, lane);
        const uint32_t* bc = b[it % 3];
        mma16816h(ch + q * 4,          areg + ks * 4,      bc[0], bc[1]);
        mma16816h(ch + q * 4 + 2,      areg + ks * 4,      bc[2], bc[3]);
        mma16816h(ch + 32 + q * 4,     areg + 32 + ks * 4, bc[0], bc[1]);
        mma16816h(ch + 32 + q * 4 + 2, areg + 32 + ks * 4, bc[2], bc[3]);
    }
}

// fused dual-B gemm for d3: two 128-col outputs from the same areg.
// 8 independent mma chains per iteration (chA + chB), shared loop.
__device__ __forceinline__ void gemm_regA2h_dual(uint32_t chA[64], uint32_t chB[64],
                                                 const uint32_t areg[64],
                                                 uint32_t bbaseA, uint32_t bbaseB, int lane) {
    uint32_t bA[3][4], bB[3][4];
    ldb4nt(bA[0], bbaseA, 0, 0, lane);
    ldb4nt(bB[0], bbaseB, 0, 0, lane);
    ldb4nt(bA[1], bbaseA, 0, 16, lane);
    ldb4nt(bB[1], bbaseB, 0, 16, lane);
    #pragma unroll
    for (int it = 0; it < 64; it++) {
        const int q  = it & 7;
        const int ks = it >> 3;
        const int itp = it + 2;
        if (itp < 64) {
            ldb4nt(bA[itp % 3], bbaseA, (itp >> 3) * 16, (itp & 7) * 16, lane);
            ldb4nt(bB[itp % 3], bbaseB, (itp >> 3) * 16, (itp & 7) * 16, lane);
        }
        const uint32_t* ba = bA[it % 3];
        const uint32_t* bb = bB[it % 3];
        const uint32_t* a0 = areg + ks * 4;
        const uint32_t* a1 = areg + 32 + ks * 4;
        mma16816h(chA + q * 4,          a0, ba[0], ba[1]);
        mma16816h(chB + q * 4,          a0, bb[0], bb[1]);
        mma16816h(chA + q * 4 + 2,      a0, ba[2], ba[3]);
        mma16816h(chB + q * 4 + 2,      a0, bb[2], bb[3]);
        mma16816h(chA + 32 + q * 4,     a1, ba[0], ba[1]);
        mma16816h(chB + 32 + q * 4,     a1, bb[0], bb[1]);
        mma16816h(chA + 32 + q * 4 + 2, a1, ba[2], ba[3]);
        mma16816h(chB + 32 + q * 4 + 2, a1, bb[2], bb[3]);
    }
}

// regA, N=16 only (e3): dh[8] = [mt(2)][4]
__device__ __forceinline__ void gemm_regA2h_n16(uint32_t dh[8], const uint32_t areg[64],
                                                uint32_t bbase, int lane) {
    uint32_t b[3][4];
    ldb4nt(b[0], bbase, 0, 0, lane);
    ldb4nt(b[1], bbase, 16, 0, lane);
    #pragma unroll
    for (int ks = 0; ks < 8; ks++) {
        const int kp = ks + 2;
        if (kp < 8) ldb4nt(b[kp % 3], bbase, kp * 16, 0, lane);
        const uint32_t* bc = b[ks % 3];
        mma16816h(dh,     areg + ks * 4,      bc[0], bc[1]);
        mma16816h(dh + 2, areg + ks * 4,      bc[2], bc[3]);
        mma16816h(dh + 4, areg + 32 + ks * 4, bc[0], bc[1]);
        mma16816h(dh + 6, areg + 32 + ks * 4, bc[2], bc[3]);
    }
}

__device__ __forceinline__ void zero64u(uint32_t ch[64]) {
    #pragma unroll
    for (int i = 0; i < 64; i++) ch[i] = 0u;
}

// bias + relu in fp16: ch -> areg
__device__ __forceinline__ void epi_pack2h(const uint32_t ch[64], uint32_t areg[64],
                                           const float* bias, int lane) {
    const int qp = lane & 3;
    #pragma unroll
    for (int q = 0; q < 8; q++) {
        float2 bA = *(const float2*)(bias + 16 * q + 2 * qp);
        float2 bB = *(const float2*)(bias + 16 * q + 8 + 2 * qp);
        uint32_t bAh = pack_h2(bA.x, bA.y);
        uint32_t bBh = pack_h2(bB.x, bB.y);
        #pragma unroll
        for (int mt = 0; mt < 2; mt++) {
            const uint32_t* cc = ch + mt * 32 + q * 4;
            uint32_t* ar = areg + mt * 32 + q * 4;
            ar[0] = hrelu2u(hadd2u(cc[0], bAh));
            ar[1] = hrelu2u(hadd2u(cc[1], bAh));
            ar[2] = hrelu2u(hadd2u(cc[2], bBh));
            ar[3] = hrelu2u(hadd2u(cc[3], bBh));
        }
    }
}

// async weight tile copy (caller commits)
__device__ __forceinline__ void copy_tile(uint32_t sb, int slot, int t, int tid) {
    uint32_t dst = sb + SLOT(slot);
    const uint8_t* src = (const uint8_t*)(g_w + (size_t)t * TSZ);
    for (int i = tid; i < TSZ / 8; i += THREADS)
        cp16(dst + i * 16, src + i * 16);
}

// fully-async gather: 1 thread per row, 16 x 16B
__device__ __forceinline__ void gather_async(uint32_t sb, const int* nodes, int tid) {
    const uint8_t* src = (const uint8_t*)(g_xh + (size_t)nodes[tid] * 128);
    uint32_t dst = sb + AOFF + (uint32_t)(tid * ROWB);
    #pragma unroll
    for (int j = 0; j < 16; j++)
        cp16(dst + j * 16, src + j * 16);
}

// recon ssq for one d3 half (fp16 chain -> fp32 here)
__device__ __forceinline__ void epi_recon2h(const uint32_t ch[64], uint8_t* sm, const float* bias,
                                            const int* nodes, int m0, int lane) {
    const int g = lane >> 2, qp = lane & 3;
    #pragma unroll
    for (int mt = 0; mt < 2; mt++) {
        const int r0 = m0 + mt * 16 + g, r1 = r0 + 8;
        const uint32_t* x0 = (const uint32_t*)(g_xh + (size_t)nodes[r0] * 128);
        const uint32_t* x1 = (const uint32_t*)(g_xh + (size_t)nodes[r1] * 128);
        float s0 = 0.f, s1 = 0.f;
        #pragma unroll
        for (int q = 0; q < 8; q++) {
            const uint32_t* cc = ch + mt * 32 + q * 4;
            float2 f0 = h22f2(cc[0]);
            float2 f1 = h22f2(cc[1]);
            float2 f2 = h22f2(cc[2]);
            float2 f3 = h22f2(cc[3]);
            int col = q * 16 + qp * 2;
            float2 bA = *(const float2*)(bias + col);
            float2 bB = *(const float2*)(bias + col + 8);
            uint32_t wa0 = x0[q * 8 + qp],     wb0 = x0[q * 8 + 4 + qp];
            uint32_t wa1 = x1[q * 8 + qp],     wb1 = x1[q * 8 + 4 + qp];
            float2 xa0 = h22f2(wa0), xb0 = h22f2(wb0);
            float2 xa1 = h22f2(wa1), xb1 = h22f2(wb1);
            float d0 = f0.x + bA.x - xa0.x, d1 = f0.y + bA.y - xa0.y;
            float d2 = f1.x + bA.x - xa1.x, d3 = f1.y + bA.y - xa1.y;
            float d4 = f2.x + bB.x - xb0.x, d5 = f2.y + bB.y - xb0.y;
            float d6 = f3.x + bB.x - xb1.x, d7 = f3.y + bB.y - xb1.y;
            s0 = fmaf(d0, d0, fmaf(d1, d1, fmaf(d4, d4, fmaf(d5, d5, s0))));
            s1 = fmaf(d2, d2, fmaf(d3, d3, fmaf(d6, d6, fmaf(d7, d7, s1))));
        }
        s0 += __shfl_xor_sync(0xFFFFFFFFu, s0, 1);
        s0 += __shfl_xor_sync(0xFFFFFFFFu, s0, 2);
        s1 += __shfl_xor_sync(0xFFFFFFFFu, s1, 1);
        s1 += __shfl_xor_sync(0xFFFFFFFFu, s1, 2);
        if (qp == 0) {
            float* rs = (float*)(sm + RS);
            rs[r0] += s0;
            rs[r1] += s1;
        }
    }
}

// ---- weight + x prep (N-major tiles) ----
__device__ void prep_one(const float* W, int kstride, int noff,
                         int nrows, int nreal, int kcols, int kreal, int tile) {
    int total = nrows * kcols;
    int gt = blockIdx.x * blockDim.x + threadIdx.x;
    int gs = gridDim.x * blockDim.x;
    for (int idx = gt; idx < total; idx += gs) {
        int n = idx / kcols, k = idx % kcols;
        float w = (n < nreal && k < kreal) ? W[(size_t)k * kstride + noff + n] : 0.f;
        g_w[(size_t)tile * TSZ + (size_t)n * STRIDE + k] =
            __half_as_ushort(__float2half_rn(w));
    }
}

__global__ void prep_kernel(Params p) {
    if (blockIdx.x == 0 && threadIdx.x == 0) { g_rsum = 0.0; g_klsum = 0.0; g_cnt = 0u; }
    int gt = blockIdx.x * blockDim.x + threadIdx.x;
    int gs = gridDim.x * blockDim.x;
    int nq = p.NX >> 2;
    const float4* xs = (const float4*)p.x;
    uint2* xd = (uint2*)g_xh;
    for (int i = gt; i < nq; i += gs) {
        float4 f = xs[i];
        xd[i] = make_uint2(pack_h2(f.x, f.y), pack_h2(f.z, f.w));
    }
    prep_one(p.eW0,                 128,   0,   128,  128,  128,  128,  T_E0A);
    prep_one(p.eW0 + 128 * 128,     128,   0,   128,  128,  128,  128,  T_E0B);
    prep_one(p.eW1,                 128,   0,   128,  128,  128,  128,  T_E1);
    prep_one(p.eW2,                 128,   0,   128,  128,  128,  128,  T_E2);
    prep_one(p.eW3,                 10,    0,   16,   10,   128,  128,  T_E3);
    prep_one(p.dW0,                 128,   0,   128,  128,  16,   5,    T_D0);
    prep_one(p.dW1,                 128,   0,   128,  128,  128,  128,  T_D1);
    prep_one(p.dW2,                 128,   0,   128,  128,  128,  128,  T_D2);
    prep_one(p.dW3,                 256,   0,   128,  128,  128,  128,  T_D3A);
    prep_one(p.dW3,                 256,   128, 128,  128,  128,  128,  T_D3B);
}

// ---- main fused VAE kernel: 1 CTA = 128 edges, 4 warps (32 rows each), 2 CTAs/SM ----
__global__ void __launch_bounds__(THREADS, 2)
vae_kernel(Params p) {
    extern __shared__ __align__(16) uint8_t sm[];
    const uint32_t sb = smem_u32(sm);
    const int tid  = threadIdx.x;
    const int lane = tid & 31;
    const int m0   = (tid >> 5) * 32;
    const int e0   = blockIdx.x * TT;

    int* rows_s = (int*)(sm + ROWS_S);
    int* cols_s = (int*)(sm + COLS_S);
    {
        int e = e0 + tid;
        bool v = e < p.E;
        rows_s[tid] = v ? p.row[e] : 0;
        cols_s[tid] = v ? p.col[e] : 0;
        ((float*)(sm + RS))[tid] = 0.f;
    }
    __syncthreads();

    // async group 0: slot0 <- E0A, all biases, row-gather -> A
    copy_tile(sb, 0, T_E0A, tid);
    cp4(sb + BIASO(0) + tid * 4, p.eb0 + tid);
    cp4(sb + BIASO(1) + tid * 4, p.eb1 + tid);
    cp4(sb + BIASO(2) + tid * 4, p.eb2 + tid);
    cp4(sb + BIASO(3) + tid * 4, p.db0 + tid);
    cp4(sb + BIASO(4) + tid * 4, p.db1 + tid);
    cp4(sb + BIASO(5) + tid * 4, p.db2 + tid);
    cp4(sb + BIASO(6) + tid * 4, p.db3 + tid);
    cp4(sb + BIASO(7) + tid * 4, p.db3 + 128 + tid);
    gather_async(sb, rows_s, tid);
    CP_COMMIT();
    CP_WAIT0();
    __syncthreads();

    uint32_t ch[64];
    uint32_t areg[64];
    zero64u(ch);

    // L0: e0 first K-half (A = x[row] smem), slot0; async slot1 <- E0B
    copy_tile(sb, 1, T_E0B, tid);
    CP_COMMIT();
    gemm_smemA2h<8>(ch, sb + AOFF, sb + SLOT(0), m0, lane);
    CP_WAIT0();
    __syncthreads();

    // col-gather (own group); slot0 <- E1 (second group)
    gather_async(sb, cols_s, tid);
    CP_COMMIT();
    copy_tile(sb, 0, T_E1, tid);
    CP_COMMIT();
    CP_WAIT1();
    __syncthreads();

    // L1: e0 second K-half (fp16 chain continues), slot1; pack eb0
    gemm_smemA2h<8>(ch, sb + AOFF, sb + SLOT(1), m0, lane);
    epi_pack2h(ch, areg, (float*)(sm + BIASO(0)), lane);
    CP_WAIT0();
    __syncthreads();

    // L2: e1, slot0 (regs); slot1 <- E2; pack eb1
    copy_tile(sb, 1, T_E2, tid);
    CP_COMMIT();
    zero64u(ch);
    gemm_regA2h(ch, areg, sb + SLOT(0), lane);
    epi_pack2h(ch, areg, (float*)(sm + BIASO(1)), lane);
    CP_WAIT0();
    __syncthreads();

    // L3: e2, slot1 (regs); slot0 <- E3; pack eb2
    copy_tile(sb, 0, T_E3, tid);
    CP_COMMIT();
    zero64u(ch);
    gemm_regA2h(ch, areg, sb + SLOT(1), lane);
    epi_pack2h(ch, areg, (float*)(sm + BIASO(2)), lane);
    CP_WAIT0();
    __syncthreads();

    // L4: e3 (N=16 incl. pad), slot0 (regs); slot1 <- D0
    copy_tile(sb, 1, T_D0, tid);
    CP_COMMIT();
    {
        uint32_t dh[8];
        #pragma unroll
        for (int i = 0; i < 8; i++) dh[i] = 0u;
        gemm_regA2h_n16(dh, areg, sb + SLOT(0), lane);
        const int g = lane >> 2, qp = lane & 3;
        #pragma unroll
        for (int mt = 0; mt < 2; mt++) {
            int r0 = m0 + mt * 16 + g, r1 = r0 + 8;
            float2 fa0 = h22f2(dh[mt * 4 + 0]);
            float2 fa1 = h22f2(dh[mt * 4 + 1]);
            float2 fb0 = h22f2(dh[mt * 4 + 2]);
            float2 fb1 = h22f2(dh[mt * 4 + 3]);
            *(float2*)(sm + AOFF + (size_t)r0 * ROWB + 64 + qp * 8)      = fa0;
            *(float2*)(sm + AOFF + (size_t)r1 * ROWB + 64 + qp * 8)      = fa1;
            *(float2*)(sm + AOFF + (size_t)r0 * ROWB + 64 + 32 + qp * 8) = fb0;
            *(float2*)(sm + AOFF + (size_t)r1 * ROWB + 64 + 32 + qp * 8) = fb1;
        }
    }
    __syncthreads();
    // per-edge reparam + KL (eps via direct LDG); z -> A cols 0..15
    {
        int r = tid, e = e0 + r;
        bool v = e < p.E;
        const float* tmp = (const float*)(sm + AOFF + (size_t)r * ROWB + 64);
        float kl = 0.f, z[5];
        #pragma unroll
        for (int l = 0; l < 5; l++) {
            float mu = tmp[l]     + p.eb3[l];
            float lv = tmp[5 + l] + p.eb3[5 + l];
            float ep = v ? p.eps[(size_t)e * 5 + l] : 0.f;
            z[l] = fmaf(ep, expf(0.5f * lv), mu);
            kl  += -0.5f * (1.f + lv - mu * mu - expf(lv));
        }
        ((float*)(sm + KLP))[r] = v ? kl * BETA : 0.f;
        uint8_t* hp = sm + AOFF + (size_t)r * ROWB;
        *(uint4*)(hp)      = make_uint4(pack_h2(z[0], z[1]), pack_h2(z[2], z[3]),
                                        pack_h2(z[4], 0.f), 0u);
        *(uint4*)(hp + 16) = make_uint4(0u, 0u, 0u, 0u);
    }
    CP_WAIT0();
    __syncthreads();

    // L5: d0 (K=16, A = z smem), slot1; slot0 <- D1; pack db0
    copy_tile(sb, 0, T_D1, tid);
    CP_COMMIT();
    zero64u(ch);
    gemm_smemA2h<1>(ch, sb + AOFF, sb + SLOT(1), m0, lane);
    epi_pack2h(ch, areg, (float*)(sm + BIASO(3)), lane);
    CP_WAIT0();
    __syncthreads();

    // L6: d1, slot0 (regs); slot1 <- D2; pack db1
    copy_tile(sb, 1, T_D2, tid);
    CP_COMMIT();
    zero64u(ch);
    gemm_regA2h(ch, areg, sb + SLOT(0), lane);
    epi_pack2h(ch, areg, (float*)(sm + BIASO(4)), lane);
    CP_WAIT0();
    __syncthreads();

    // L7: d2, slot1 (regs); slot0 <- D3A; pack db2
    copy_tile(sb, 0, T_D3A, tid);
    CP_COMMIT();
    zero64u(ch);
    gemm_regA2h(ch, areg, sb + SLOT(1), lane);
    epi_pack2h(ch, areg, (float*)(sm + BIASO(5)), lane);
    CP_WAIT0();
    __syncthreads();

    // L8+L9 fused: slot1 <- D3B first, wait, then dual gemm over both halves
    copy_tile(sb, 1, T_D3B, tid);
    CP_COMMIT();
    CP_WAIT0();
    __syncthreads();
    {
        uint32_t chB[64];
        zero64u(ch);
        zero64u(chB);
        gemm_regA2h_dual(ch, chB, areg, sb + SLOT(0), sb + SLOT(1), lane);
        epi_recon2h(ch,  sm, (float*)(sm + BIASO(6)), rows_s, m0, lane);
        epi_recon2h(chB, sm, (float*)(sm + BIASO(7)), cols_s, m0, lane);
    }
    __syncthreads();

    // finalize: affinities + block reduction
    float rl, kl;
    {
        int e = e0 + tid;
        bool v = e < p.E;
        float ssq = ((float*)(sm + RS))[tid];
        rl = v ? sqrtf(ssq) : 0.f;
        kl = ((float*)(sm + KLP))[tid];
        if (v) p.out[e] = 1.0f / fmaf(V2C, rl, 1.0f);
    }
    float s1 = rl, s2 = kl;
    #pragma unroll
    for (int o = 16; o; o >>= 1) {
        s1 += __shfl_down_sync(0xFFFFFFFFu, s1, o);
        s2 += __shfl_down_sync(0xFFFFFFFFu, s2, o);
    }
    float* red = (float*)(sm + RED);
    if (lane == 0) { red[tid >> 5] = s1; red[4 + (tid >> 5)] = s2; }
    __syncthreads();
    if (tid == 0) {
        float a = red[0] + red[1] + red[2] + red[3];
        float b = red[4] + red[5] + red[6] + red[7];
        atomicAdd(&g_rsum,  (double)a);
        atomicAdd(&g_klsum, (double)b);
        __threadfence();
        unsigned int t = atomicAdd(&g_cnt, 1u);
        if (t == gridDim.x - 1) {
            double rs = atomicAdd(&g_rsum,  0.0);
            double ks = atomicAdd(&g_klsum, 0.0);
            p.out[p.E]     = (float)(rs / (double)p.E);
            p.out[p.E + 1] = (float)(ks / ((double)p.E * 5.0));
        }
    }
}

// ---------------------------------------------------------------------------
extern "C" void kernel_launch(void* const* d_in, const int* in_sizes, int n_in,
                              void* d_out, int out_size) {
    Params p;
    p.x   = (const float*)d_in[0];
    p.row = (const int*)  d_in[1];
    p.col = (const int*)  d_in[2];
    p.eps = (const float*)d_in[3];
    p.eW0 = (const float*)d_in[4];   p.eb0 = (const float*)d_in[5];
    p.eW1 = (const float*)d_in[6];   p.eb1 = (const float*)d_in[7];
    p.eW2 = (const float*)d_in[8];   p.eb2 = (const float*)d_in[9];
    p.eW3 = (const float*)d_in[10];  p.eb3 = (const float*)d_in[11];
    p.dW0 = (const float*)d_in[12];  p.db0 = (const float*)d_in[13];
    p.dW1 = (const float*)d_in[14];  p.db1 = (const float*)d_in[15];
    p.dW2 = (const float*)d_in[16];  p.db2 = (const float*)d_in[17];
    p.dW3 = (const float*)d_in[18];  p.db3 = (const float*)d_in[19];
    p.out = (float*)d_out;
    p.E   = in_sizes[1];
    p.NX  = in_sizes[0];

    cudaFuncSetAttribute(vae_kernel,
                         cudaFuncAttributeMaxDynamicSharedMemorySize, SMEM_TOTAL);

    const int tiles = (p.E + TT - 1) / TT;
    prep_kernel<<<2048, 256>>>(p);
    vae_kernel<<<tiles, THREADS, SMEM_TOTAL>>>(p);
}

// round 17
// speedup vs baseline: 1.0499x; 1.0499x over previous
#include <cuda_runtime.h>
#include <cuda_fp16.h>
#include <cstdint>

#define THREADS 128
#define TT      128
#define STRIDE  136                 // fp16 elems per smem row (128 + 8 pad)
#define ROWB    (STRIDE * 2)        // 272 bytes per row
#define TSZ     (128 * STRIDE)      // elems per weight tile
#define NNODE   100000
#define BETA    10.0f
#define V2C     3.5f

__device__ double g_rsum, g_klsum;
__device__ unsigned int g_cnt;

// 10 weight tiles, fp16, N-MAJOR [n][k] layout with row stride 136
enum { T_E0A, T_E0B, T_E1, T_E2, T_E3, T_D0, T_D1, T_D2, T_D3A, T_D3B };
__device__ __align__(16) uint16_t g_w[10 * TSZ];
__device__ __align__(16) uint16_t g_xh[NNODE * 128];

// ---- smem byte offsets ----
#define AOFF      0
#define SLOT(s)   (34816 + (s) * 34816)
#define BIASO(b)  (104448 + (b) * 512)
#define ROWS_S    108544
#define COLS_S    109056
#define KLP       109568
#define RS        110080
#define RED       110592
#define EPS_S     110656
#define SMEM_TOTAL (110656 + 2560)

struct Params {
    const float* x; const int* row; const int* col; const float* eps;
    const float *eW0,*eb0,*eW1,*eb1,*eW2,*eb2,*eW3,*eb3;
    const float *dW0,*db0,*dW1,*db1,*dW2,*db2,*dW3,*db3;
    float* out; int E; int NX;
};

// ---- helpers ----
__device__ __forceinline__ uint32_t smem_u32(const void* p) {
    uint32_t a;
    asm("{ .reg .u64 t; cvta.to.shared.u64 t, %1; cvt.u32.u64 %0, t; }" : "=r"(a) : "l"(p));
    return a;
}
__device__ __forceinline__ uint32_t pack_h2(float a, float b) {
    __half2 h = __floats2half2_rn(a, b);
    return *(uint32_t*)&h;
}
__device__ __forceinline__ uint32_t hrelu2u(uint32_t a) {
    __half2 z = __float2half2_rn(0.f);
    __half2 r = __hmax2(*(__half2*)&a, z);
    return *(uint32_t*)&r;
}
__device__ __forceinline__ float2 h22f2(uint32_t a) {
    return __half22float2(*(__half2*)&a);
}

__device__ __forceinline__ void cp16(uint32_t dst, const void* src) {
    asm volatile("cp.async.cg.shared.global [%0], [%1], 16;" :: "r"(dst), "l"(src));
}
__device__ __forceinline__ void cp4(uint32_t dst, const void* src) {
    asm volatile("cp.async.ca.shared.global [%0], [%1], 4;" :: "r"(dst), "l"(src));
}
#define CP_COMMIT() asm volatile("cp.async.commit_group;" ::: "memory")
#define CP_WAIT0()  asm volatile("cp.async.wait_group 0;"  ::: "memory")
#define CP_WAIT1()  asm volatile("cp.async.wait_group 1;"  ::: "memory")

// A fragment: 16x16 row-major at (m0, k0), non-trans ldmatrix.x4
__device__ __forceinline__ void lda4(uint32_t a[4], uint32_t base, int m0, int k0, int lane) {
    uint32_t addr = base + (uint32_t)(((m0 + (lane & 7) + ((lane & 8) ? 8 : 0)) * STRIDE
                                   + k0 + ((lane & 16) ? 8 : 0)) << 1);
    asm volatile("ldmatrix.sync.aligned.m8n8.x4.shared.b16 {%0,%1,%2,%3}, [%4];"
        : "=r"(a[0]), "=r"(a[1]), "=r"(a[2]), "=r"(a[3]) : "r"(addr));
}

// B fragments from N-MAJOR storage: logical 16(k) x 16(n) at (k0, n0)
__device__ __forceinline__ void ldb4nt(uint32_t b[4], uint32_t base, int k0, int n0, int lane) {
    uint32_t addr = base + (uint32_t)(((n0 + (lane & 7) + ((lane & 16) ? 8 : 0)) * STRIDE
                                   + k0 + ((lane & 8) ? 8 : 0)) << 1);
    asm volatile("ldmatrix.sync.aligned.m8n8.x4.shared.b16 {%0,%1,%2,%3}, [%4];"
        : "=r"(b[0]), "=r"(b[1]), "=r"(b[2]), "=r"(b[3]) : "r"(addr));
}

// fp16-accumulate mma: d (2 regs) chained in place
__device__ __forceinline__ void mma16816h(uint32_t* d, const uint32_t a[4],
                                          uint32_t b0, uint32_t b1) {
    asm volatile("mma.sync.aligned.m16n8k16.row.col.f16.f16.f16.f16 "
        "{%0,%1}, {%2,%3,%4,%5}, {%6,%7}, {%0,%1};"
        : "+r"(d[0]), "+r"(d[1])
        : "r"(a[0]), "r"(a[1]), "r"(a[2]), "r"(a[3]), "r"(b0), "r"(b1));
}

// ---- 32-row warp tile GEMMs, fp16 accumulators, 2-deep B prefetch ----
// ch[64]: [mt(2)][q(8)][4]

template<int KS>
__device__ __forceinline__ void gemm_smemA2h(uint32_t ch[64], uint32_t abase, uint32_t bbase,
                                             int m0, int lane) {
    constexpr int NIT = KS * 8;
    uint32_t a[2][2][4];
    uint32_t b[3][4];
    lda4(a[0][0], abase, m0,      0, lane);
    lda4(a[0][1], abase, m0 + 16, 0, lane);
    ldb4nt(b[0], bbase, 0, 0, lane);
    if (NIT > 1) ldb4nt(b[1], bbase, (1 >> 3) * 16, (1 & 7) * 16, lane);
    #pragma unroll
    for (int it = 0; it < NIT; it++) {
        const int q  = it & 7;
        const int ks = it >> 3;
        const int itp = it + 2;
        if (itp < NIT)
            ldb4nt(b[itp % 3], bbase, (itp >> 3) * 16, (itp & 7) * 16, lane);
        if (q == 0 && ks + 1 < KS) {
            lda4(a[(ks + 1) & 1][0], abase, m0,      (ks + 1) * 16, lane);
            lda4(a[(ks + 1) & 1][1], abase, m0 + 16, (ks + 1) * 16, lane);
        }
        const uint32_t* bc = b[it % 3];
        mma16816h(ch + q * 4,          a[ks & 1][0], bc[0], bc[1]);
        mma16816h(ch + q * 4 + 2,      a[ks & 1][0], bc[2], bc[3]);
        mma16816h(ch + 32 + q * 4,     a[ks & 1][1], bc[0], bc[1]);
        mma16816h(ch + 32 + q * 4 + 2, a[ks & 1][1], bc[2], bc[3]);
    }
}

__device__ __forceinline__ void gemm_regA2h(uint32_t ch[64], const uint32_t areg[64],
                                            uint32_t bbase, int lane) {
    uint32_t b[3][4];
    ldb4nt(b[0], bbase, 0, 0, lane);
    ldb4nt(b[1], bbase, 0, 16, lane);
    #pragma unroll
    for (int it = 0; it < 64; it++) {
        const int q  = it & 7;
        const int ks = it >> 3;
        const int itp = it + 2;
        if (itp < 64)
            ldb4nt(b[itp % 3], bbase, (itp >> 3) * 16, (itp & 7) * 16, lane);
        const uint32_t* bc = b[it % 3];
        mma16816h(ch + q * 4,          areg + ks * 4,      bc[0], bc[1]);
        mma16816h(ch + q * 4 + 2,      areg + ks * 4,      bc[2], bc[3]);
        mma16816h(ch + 32 + q * 4,     areg + 32 + ks * 4, bc[0], bc[1]);
        mma16816h(ch + 32 + q * 4 + 2, areg + 32 + ks * 4, bc[2], bc[3]);
    }
}

// regA, N=16 only (e3): dh[8] = [mt(2)][4]
__device__ __forceinline__ void gemm_regA2h_n16(uint32_t dh[8], const uint32_t areg[64],
                                                uint32_t bbase, int lane) {
    uint32_t b[3][4];
    ldb4nt(b[0], bbase, 0, 0, lane);
    ldb4nt(b[1], bbase, 16, 0, lane);
    #pragma unroll
    for (int ks = 0; ks < 8; ks++) {
        const int kp = ks + 2;
        if (kp < 8) ldb4nt(b[kp % 3], bbase, kp * 16, 0, lane);
        const uint32_t* bc = b[ks % 3];
        mma16816h(dh,     areg + ks * 4,      bc[0], bc[1]);
        mma16816h(dh + 2, areg + ks * 4,      bc[2], bc[3]);
        mma16816h(dh + 4, areg + 32 + ks * 4, bc[0], bc[1]);
        mma16816h(dh + 6, areg + 32 + ks * 4, bc[2], bc[3]);
    }
}

__device__ __forceinline__ void zero8u(uint32_t d[8]) {
    #pragma unroll
    for (int i = 0; i < 8; i++) d[i] = 0u;
}

// init accumulators with per-column bias (fp16); replaces zero-init + epilogue add
__device__ __forceinline__ void bias2ch(uint32_t ch[64], const float* bias, int lane) {
    const int qp = lane & 3;
    #pragma unroll
    for (int q = 0; q < 8; q++) {
        float2 bA = *(const float2*)(bias + 16 * q + 2 * qp);
        float2 bB = *(const float2*)(bias + 16 * q + 8 + 2 * qp);
        uint32_t bAh = pack_h2(bA.x, bA.y);
        uint32_t bBh = pack_h2(bB.x, bB.y);
        #pragma unroll
        for (int mt = 0; mt < 2; mt++) {
            uint32_t* cc = ch + mt * 32 + q * 4;
            cc[0] = bAh; cc[1] = bAh;       // d0 (rows g), d1 (rows g+8): same cols
            cc[2] = bBh; cc[3] = bBh;
        }
    }
}

// relu-only pack: ch -> areg (bias already inside accumulators)
__device__ __forceinline__ void epi_relu2h(const uint32_t ch[64], uint32_t areg[64]) {
    #pragma unroll
    for (int i = 0; i < 64; i++) areg[i] = hrelu2u(ch[i]);
}

// async weight tile copy (caller commits)
__device__ __forceinline__ void copy_tile(uint32_t sb, int slot, int t, int tid) {
    uint32_t dst = sb + SLOT(slot);
    const uint8_t* src = (const uint8_t*)(g_w + (size_t)t * TSZ);
    for (int i = tid; i < TSZ / 8; i += THREADS)
        cp16(dst + i * 16, src + i * 16);
}

// fully-async gather: 1 thread per row, 16 x 16B
__device__ __forceinline__ void gather_async(uint32_t sb, const int* nodes, int tid) {
    const uint8_t* src = (const uint8_t*)(g_xh + (size_t)nodes[tid] * 128);
    uint32_t dst = sb + AOFF + (uint32_t)(tid * ROWB);
    #pragma unroll
    for (int j = 0; j < 16; j++)
        cp16(dst + j * 16, src + j * 16);
}

// recon ssq for one d3 half (bias pre-folded into ch)
__device__ __forceinline__ void epi_recon2h(const uint32_t ch[64], uint8_t* sm,
                                            const int* nodes, int m0, int lane) {
    const int g = lane >> 2, qp = lane & 3;
    #pragma unroll
    for (int mt = 0; mt < 2; mt++) {
        const int r0 = m0 + mt * 16 + g, r1 = r0 + 8;
        const uint32_t* x0 = (const uint32_t*)(g_xh + (size_t)nodes[r0] * 128);
        const uint32_t* x1 = (const uint32_t*)(g_xh + (size_t)nodes[r1] * 128);
        float s0 = 0.f, s1 = 0.f;
        #pragma unroll
        for (int q = 0; q < 8; q++) {
            const uint32_t* cc = ch + mt * 32 + q * 4;
            float2 f0 = h22f2(cc[0]);
            float2 f1 = h22f2(cc[1]);
            float2 f2 = h22f2(cc[2]);
            float2 f3 = h22f2(cc[3]);
            uint32_t wa0 = x0[q * 8 + qp],     wb0 = x0[q * 8 + 4 + qp];
            uint32_t wa1 = x1[q * 8 + qp],     wb1 = x1[q * 8 + 4 + qp];
            float2 xa0 = h22f2(wa0), xb0 = h22f2(wb0);
            float2 xa1 = h22f2(wa1), xb1 = h22f2(wb1);
            float d0 = f0.x - xa0.x, d1 = f0.y - xa0.y;
            float d2 = f1.x - xa1.x, d3 = f1.y - xa1.y;
            float d4 = f2.x - xb0.x, d5 = f2.y - xb0.y;
            float d6 = f3.x - xb1.x, d7 = f3.y - xb1.y;
            s0 = fmaf(d0, d0, fmaf(d1, d1, fmaf(d4, d4, fmaf(d5, d5, s0))));
            s1 = fmaf(d2, d2, fmaf(d3, d3, fmaf(d6, d6, fmaf(d7, d7, s1))));
        }
        s0 += __shfl_xor_sync(0xFFFFFFFFu, s0, 1);
        s0 += __shfl_xor_sync(0xFFFFFFFFu, s0, 2);
        s1 += __shfl_xor_sync(0xFFFFFFFFu, s1, 1);
        s1 += __shfl_xor_sync(0xFFFFFFFFu, s1, 2);
        if (qp == 0) {
            float* rs = (float*)(sm + RS);
            rs[r0] += s0;
            rs[r1] += s1;
        }
    }
}

// ---- weight + x prep (N-major tiles) ----
__device__ void prep_one(const float* W, int kstride, int noff,
                         int nrows, int nreal, int kcols, int kreal, int tile) {
    int total = nrows * kcols;
    int gt = blockIdx.x * blockDim.x + threadIdx.x;
    int gs = gridDim.x * blockDim.x;
    for (int idx = gt; idx < total; idx += gs) {
        int n = idx / kcols, k = idx % kcols;
        float w = (n < nreal && k < kreal) ? W[(size_t)k * kstride + noff + n] : 0.f;
        g_w[(size_t)tile * TSZ + (size_t)n * STRIDE + k] =
            __half_as_ushort(__float2half_rn(w));
    }
}

__global__ void prep_kernel(Params p) {
    if (blockIdx.x == 0 && threadIdx.x == 0) { g_rsum = 0.0; g_klsum = 0.0; g_cnt = 0u; }
    int gt = blockIdx.x * blockDim.x + threadIdx.x;
    int gs = gridDim.x * blockDim.x;
    int nq = p.NX >> 2;
    const float4* xs = (const float4*)p.x;
    uint2* xd = (uint2*)g_xh;
    for (int i = gt; i < nq; i += gs) {
        float4 f = xs[i];
        xd[i] = make_uint2(pack_h2(f.x, f.y), pack_h2(f.z, f.w));
    }
    prep_one(p.eW0,                 128,   0,   128,  128,  128,  128,  T_E0A);
    prep_one(p.eW0 + 128 * 128,     128,   0,   128,  128,  128,  128,  T_E0B);
    prep_one(p.eW1,                 128,   0,   128,  128,  128,  128,  T_E1);
    prep_one(p.eW2,                 128,   0,   128,  128,  128,  128,  T_E2);
    prep_one(p.eW3,                 10,    0,   16,   10,   128,  128,  T_E3);
    prep_one(p.dW0,                 128,   0,   128,  128,  16,   5,    T_D0);
    prep_one(p.dW1,                 128,   0,   128,  128,  128,  128,  T_D1);
    prep_one(p.dW2,                 128,   0,   128,  128,  128,  128,  T_D2);
    prep_one(p.dW3,                 256,   0,   128,  128,  128,  128,  T_D3A);
    prep_one(p.dW3,                 256,   128, 128,  128,  128,  128,  T_D3B);
}

// ---- main fused VAE kernel: 1 CTA = 128 edges, 4 warps (32 rows each), 2 CTAs/SM ----
__global__ void __launch_bounds__(THREADS, 2)
vae_kernel(Params p) {
    extern __shared__ __align__(16) uint8_t sm[];
    const uint32_t sb = smem_u32(sm);
    const int tid  = threadIdx.x;
    const int lane = tid & 31;
    const int m0   = (tid >> 5) * 32;
    const int e0   = blockIdx.x * TT;

    int* rows_s = (int*)(sm + ROWS_S);
    int* cols_s = (int*)(sm + COLS_S);
    {
        int e = e0 + tid;
        bool v = e < p.E;
        rows_s[tid] = v ? p.row[e] : 0;
        cols_s[tid] = v ? p.col[e] : 0;
        ((float*)(sm + RS))[tid] = 0.f;
    }
    __syncthreads();

    // async group 0: slot0 <- E0A, all biases, eps tile (guarded), row-gather -> A
    copy_tile(sb, 0, T_E0A, tid);
    cp4(sb + BIASO(0) + tid * 4, p.eb0 + tid);
    cp4(sb + BIASO(1) + tid * 4, p.eb1 + tid);
    cp4(sb + BIASO(2) + tid * 4, p.eb2 + tid);
    cp4(sb + BIASO(3) + tid * 4, p.db0 + tid);
    cp4(sb + BIASO(4) + tid * 4, p.db1 + tid);
    cp4(sb + BIASO(5) + tid * 4, p.db2 + tid);
    cp4(sb + BIASO(6) + tid * 4, p.db3 + tid);
    cp4(sb + BIASO(7) + tid * 4, p.db3 + 128 + tid);
    for (int i = tid; i < 160; i += THREADS) {
        size_t off = (size_t)e0 * 5 + (size_t)i * 4;
        if (off + 4 <= (size_t)p.E * 5)
            cp16(sb + EPS_S + i * 16, p.eps + off);
    }
    gather_async(sb, rows_s, tid);
    CP_COMMIT();
    CP_WAIT0();
    __syncthreads();

    uint32_t ch[64];
    uint32_t areg[64];
    bias2ch(ch, (float*)(sm + BIASO(0)), lane);   // eb0 folded into e0 chain

    // L0: e0 first K-half (A = x[row] smem), slot0; async slot1 <- E0B
    copy_tile(sb, 1, T_E0B, tid);
    CP_COMMIT();
    gemm_smemA2h<8>(ch, sb + AOFF, sb + SLOT(0), m0, lane);
    CP_WAIT0();
    __syncthreads();

    // col-gather (own group); slot0 <- E1 (second group)
    gather_async(sb, cols_s, tid);
    CP_COMMIT();
    copy_tile(sb, 0, T_E1, tid);
    CP_COMMIT();
    CP_WAIT1();
    __syncthreads();

    // L1: e0 second K-half (chain continues), slot1; relu-pack
    gemm_smemA2h<8>(ch, sb + AOFF, sb + SLOT(1), m0, lane);
    epi_relu2h(ch, areg);
    CP_WAIT0();
    __syncthreads();

    // L2: e1, slot0 (regs); slot1 <- E2
    copy_tile(sb, 1, T_E2, tid);
    CP_COMMIT();
    bias2ch(ch, (float*)(sm + BIASO(1)), lane);
    gemm_regA2h(ch, areg, sb + SLOT(0), lane);
    epi_relu2h(ch, areg);
    CP_WAIT0();
    __syncthreads();

    // L3: e2, slot1 (regs); slot0 <- E3
    copy_tile(sb, 0, T_E3, tid);
    CP_COMMIT();
    bias2ch(ch, (float*)(sm + BIASO(2)), lane);
    gemm_regA2h(ch, areg, sb + SLOT(1), lane);
    epi_relu2h(ch, areg);
    CP_WAIT0();
    __syncthreads();

    // L4: e3 (N=16 incl. pad), slot0 (regs); slot1 <- D0
    copy_tile(sb, 1, T_D0, tid);
    CP_COMMIT();
    {
        uint32_t dh[8];
        zero8u(dh);
        gemm_regA2h_n16(dh, areg, sb + SLOT(0), lane);
        const int g = lane >> 2, qp = lane & 3;
        #pragma unroll
        for (int mt = 0; mt < 2; mt++) {
            int r0 = m0 + mt * 16 + g, r1 = r0 + 8;
            float2 fa0 = h22f2(dh[mt * 4 + 0]);
            float2 fa1 = h22f2(dh[mt * 4 + 1]);
            float2 fb0 = h22f2(dh[mt * 4 + 2]);
            float2 fb1 = h22f2(dh[mt * 4 + 3]);
            *(float2*)(sm + AOFF + (size_t)r0 * ROWB + 64 + qp * 8)      = fa0;
            *(float2*)(sm + AOFF + (size_t)r1 * ROWB + 64 + qp * 8)      = fa1;
            *(float2*)(sm + AOFF + (size_t)r0 * ROWB + 64 + 32 + qp * 8) = fb0;
            *(float2*)(sm + AOFF + (size_t)r1 * ROWB + 64 + 32 + qp * 8) = fb1;
        }
    }
    __syncthreads();
    // per-edge reparam + KL; z -> A cols 0..15 (fp16, zero-padded)
    {
        int r = tid, e = e0 + r;
        bool v = e < p.E;
        const float* tmp   = (const float*)(sm + AOFF + (size_t)r * ROWB + 64);
        const float* eps_s = (const float*)(sm + EPS_S);
        float kl = 0.f, z[5];
        #pragma unroll
        for (int l = 0; l < 5; l++) {
            float mu = tmp[l]     + p.eb3[l];
            float lv = tmp[5 + l] + p.eb3[5 + l];
            float ep = v ? eps_s[r * 5 + l] : 0.f;
            z[l] = fmaf(ep, expf(0.5f * lv), mu);
            kl  += -0.5f * (1.f + lv - mu * mu - expf(lv));
        }
        ((float*)(sm + KLP))[r] = v ? kl * BETA : 0.f;
        uint8_t* hp = sm + AOFF + (size_t)r * ROWB;
        *(uint4*)(hp)      = make_uint4(pack_h2(z[0], z[1]), pack_h2(z[2], z[3]),
                                        pack_h2(z[4], 0.f), 0u);
        *(uint4*)(hp + 16) = make_uint4(0u, 0u, 0u, 0u);
    }
    CP_WAIT0();
    __syncthreads();

    // L5: d0 (K=16, A = z smem), slot1; slot0 <- D1
    copy_tile(sb, 0, T_D1, tid);
    CP_COMMIT();
    bias2ch(ch, (float*)(sm + BIASO(3)), lane);
    gemm_smemA2h<1>(ch, sb + AOFF, sb + SLOT(1), m0, lane);
    epi_relu2h(ch, areg);
    CP_WAIT0();
    __syncthreads();

    // L6: d1, slot0 (regs); slot1 <- D2
    copy_tile(sb, 1, T_D2, tid);
    CP_COMMIT();
    bias2ch(ch, (float*)(sm + BIASO(4)), lane);
    gemm_regA2h(ch, areg, sb + SLOT(0), lane);
    epi_relu2h(ch, areg);
    CP_WAIT0();
    __syncthreads();

    // L7: d2, slot1 (regs); slot0 <- D3A
    copy_tile(sb, 0, T_D3A, tid);
    CP_COMMIT();
    bias2ch(ch, (float*)(sm + BIASO(5)), lane);
    gemm_regA2h(ch, areg, sb + SLOT(1), lane);
    epi_relu2h(ch, areg);
    CP_WAIT0();
    __syncthreads();

    // L8: d3a, slot0 (regs, areg preserved); slot1 <- D3B; recon vs x[row]
    copy_tile(sb, 1, T_D3B, tid);
    CP_COMMIT();
    bias2ch(ch, (float*)(sm + BIASO(6)), lane);
    gemm_regA2h(ch, areg, sb + SLOT(0), lane);
    epi_recon2h(ch, sm, rows_s, m0, lane);
    CP_WAIT0();
    __syncthreads();

    // L9: d3b, slot1 (same areg); recon vs x[col]
    bias2ch(ch, (float*)(sm + BIASO(7)), lane);
    gemm_regA2h(ch, areg, sb + SLOT(1), lane);
    epi_recon2h(ch, sm, cols_s, m0, lane);
    __syncthreads();

    // finalize: affinities + block reduction
    float rl, kl;
    {
        int e = e0 + tid;
        bool v = e < p.E;
        float ssq = ((float*)(sm + RS))[tid];
        rl = v ? sqrtf(ssq) : 0.f;
        kl = ((float*)(sm + KLP))[tid];
        if (v) p.out[e] = 1.0f / fmaf(V2C, rl, 1.0f);
    }
    float s1 = rl, s2 = kl;
    #pragma unroll
    for (int o = 16; o; o >>= 1) {
        s1 += __shfl_down_sync(0xFFFFFFFFu, s1, o);
        s2 += __shfl_down_sync(0xFFFFFFFFu, s2, o);
    }
    float* red = (float*)(sm + RED);
    if (lane == 0) { red[tid >> 5] = s1; red[4 + (tid >> 5)] = s2; }
    __syncthreads();
    if (tid == 0) {
        float a = red[0] + red[1] + red[2] + red[3];
        float b = red[4] + red[5] + red[6] + red[7];
        atomicAdd(&g_rsum,  (double)a);
        atomicAdd(&g_klsum, (double)b);
        __threadfence();
        unsigned int t = atomicAdd(&g_cnt, 1u);
        if (t == gridDim.x - 1) {
            double rs = atomicAdd(&g_rsum,  0.0);
            double ks = atomicAdd(&g_klsum, 0.0);
            p.out[p.E]     = (float)(rs / (double)p.E);
            p.out[p.E + 1] = (float)(ks / ((double)p.E * 5.0));
        }
    }
}

// ---------------------------------------------------------------------------
extern "C" void kernel_launch(void* const* d_in, const int* in_sizes, int n_in,
                              void* d_out, int out_size) {
    Params p;
    p.x   = (const float*)d_in[0];
    p.row = (const int*)  d_in[1];
    p.col = (const int*)  d_in[2];
    p.eps = (const float*)d_in[3];
    p.eW0 = (const float*)d_in[4];   p.eb0 = (const float*)d_in[5];
    p.eW1 = (const float*)d_in[6];   p.eb1 = (const float*)d_in[7];
    p.eW2 = (const float*)d_in[8];   p.eb2 = (const float*)d_in[9];
    p.eW3 = (const float*)d_in[10];  p.eb3 = (const float*)d_in[11];
    p.dW0 = (const float*)d_in[12];  p.db0 = (const float*)d_in[13];
    p.dW1 = (const float*)d_in[14];  p.db1 = (const float*)d_in[15];
    p.dW2 = (const float*)d_in[16];  p.db2 = (const float*)d_in[17];
    p.dW3 = (const float*)d_in[18];  p.db3 = (const float*)d_in[19];
    p.out = (float*)d_out;
    p.E   = in_sizes[1];
    p.NX  = in_sizes[0];

    cudaFuncSetAttribute(vae_kernel,
                         cudaFuncAttributeMaxDynamicSharedMemorySize, SMEM_TOTAL);

    const int tiles = (p.E + TT - 1) / TT;
    prep_kernel<<<2048, 256>>>(p);
    vae_kernel<<<tiles, THREADS, SMEM_TOTAL>>>(p);
}